// round 7
// baseline (speedup 1.0000x reference)
#include <cuda_runtime.h>
#include <cuda_bf16.h>
#include <math.h>

#define NB  4
#define NT  256
#define NV  1024
#define NS  64
#define ND  1024
#define NCV 256
#define NBT (NB*NT)

// ---------------- scratch (device globals; no allocs allowed) ----------------
__device__ __nv_bfloat16  g_Wu16[NCV*ND];
__device__ __nv_bfloat16  g_WkT16[ND*ND];    // Wk^T  (n,k) k-contiguous
__device__ __nv_bfloat16  g_WvT16[ND*ND];    // Wv^T
__device__ __nv_bfloat16  g_x16[NBT*ND];
__device__ __nv_bfloat16  g_vis16[NB*NV*NCV];
__device__ __nv_bfloat16  g_P1_16[NCV*ND];   // P1 (256 rows, k=1024) k-contig
__device__ __nv_bfloat16  g_P2T16[ND*NCV];   // P2^T (1024 rows, k=256) k-contig
__device__ __nv_bfloat16  g_G16[NBT*NCV];
__device__ float g_rvec[ND];       // bu @ Wk
__device__ float g_bo[ND];         // bu @ Wv
__device__ float g_Zh[2][NBT*NCV]; // Z split-K halves (summed in qk staging)
__device__ int   g_idx[NBT*NS];
__device__ float g_qk[NBT*NS];
__device__ float g_m[NBT], g_l[NBT];
__device__ float g_w[NBT];
__device__ int   g_flags;

// ---------------- helpers ----------------
__device__ __forceinline__ void mma_bf16(float* c, const unsigned* a, const unsigned* b) {
    asm volatile(
        "mma.sync.aligned.m16n8k16.row.col.f32.bf16.bf16.f32 "
        "{%0,%1,%2,%3}, {%4,%5,%6,%7}, {%8,%9}, {%0,%1,%2,%3};"
        : "+f"(c[0]), "+f"(c[1]), "+f"(c[2]), "+f"(c[3])
        : "r"(a[0]), "r"(a[1]), "r"(a[2]), "r"(a[3]), "r"(b[0]), "r"(b[1]));
}
__device__ __forceinline__ void cp16(void* smem, const void* g) {
    unsigned s = (unsigned)__cvta_generic_to_shared(smem);
    asm volatile("cp.async.cg.shared.global [%0], [%1], 16;\n" :: "r"(s), "l"(g));
}
__device__ __forceinline__ void cp_commit() {
    asm volatile("cp.async.commit_group;\n");
}
__device__ __forceinline__ void cp_wait1() {
    asm volatile("cp.async.wait_group 1;\n");
}
__device__ __forceinline__ void st_bf16x4(__nv_bfloat16* p, float4 v) {
    __nv_bfloat162 lo = __floats2bfloat162_rn(v.x, v.y);
    __nv_bfloat162 hi = __floats2bfloat162_rn(v.z, v.w);
    uint2 u;
    u.x = *(unsigned*)&lo;
    u.y = *(unsigned*)&hi;
    *(uint2*)p = u;
}

// ---------------- fused prep: detect + rbo + convert + transpose-convert ----
// block ranges: [0,32) detect | [32,64) rbo | [64,320) Wu conv |
// [320,1344) x conv | [1344,2368) vision conv | [2368,4416) WkT/WvT tiles
__global__ __launch_bounds__(256) void prep_kernel(
        const float* __restrict__ Wu, const float* __restrict__ Wk,
        const float* __restrict__ Wv, const float* __restrict__ x,
        const float* __restrict__ vision, const float* __restrict__ bu,
        const unsigned* __restrict__ mask) {
    __shared__ float sh[32][33];
    int blk = blockIdx.x, tid = threadIdx.x;
    if (blk < 32) {                              // mask format detection
        int f = 0;
        for (int i = blk * 256 + tid; i < 32768; i += 32 * 256) {
            unsigned w = mask[i];
            if (w > 1u)           f |= 1;
            if (w == 0x3F800000u) f |= 2;
            if (w == 0x3F803F80u) f |= 4;
            if (w == 0x00003F80u) f |= 8;
        }
        if (f) atomicOr(&g_flags, f);
        return;
    }
    blk -= 32;
    if (blk < 32) {                              // rvec = bu@Wk, bo = bu@Wv
        const float* W = (blk < 16) ? Wk : Wv;
        int jbase = (blk & 15) * 64;
        int jl = tid & 63, isl = tid >> 6;
        int j = jbase + jl;
        float s = 0.f;
        int i0 = isl * 256;
        #pragma unroll 8
        for (int i = 0; i < 256; i++) {
            int ii = i0 + i;
            s += bu[ii] * W[(size_t)ii * ND + j];
        }
        ((float*)sh)[tid] = s;
        __syncthreads();
        if (isl == 0) {
            float* r = (float*)sh;
            float tot = r[jl] + r[64 + jl] + r[128 + jl] + r[192 + jl];
            if (blk < 16) g_rvec[j] = tot; else g_bo[j] = tot;
        }
        return;
    }
    blk -= 32;
    if (blk < 256) {                             // Wu -> bf16
        int q = blk * 256 + tid;
        st_bf16x4(&g_Wu16[q * 4], ((const float4*)Wu)[q]);
        return;
    }
    blk -= 256;
    if (blk < 1024) {                            // x -> bf16
        int q = blk * 256 + tid;
        st_bf16x4(&g_x16[q * 4], ((const float4*)x)[q]);
        return;
    }
    blk -= 1024;
    if (blk < 1024) {                            // vision -> bf16
        int q = blk * 256 + tid;
        st_bf16x4(&g_vis16[q * 4], ((const float4*)vision)[q]);
        return;
    }
    blk -= 1024;
    {                                            // transpose-convert Wk / Wv
        int mat = blk >> 10;                     // 0 = Wk, 1 = Wv
        int tt = blk & 1023;
        int Tr = (tt >> 5) * 32, Tc = (tt & 31) * 32;
        const float* M = mat ? Wv : Wk;
        __nv_bfloat16* O = mat ? g_WvT16 : g_WkT16;
        int r = tid >> 5, c = tid & 31;
        #pragma unroll
        for (int i = 0; i < 4; i++)
            sh[r + 8 * i][c] = M[(size_t)(Tr + r + 8 * i) * ND + Tc + c];
        __syncthreads();
        int ci = tid >> 3, rp = (tid & 7) * 2;
        #pragma unroll
        for (int j = 0; j < 2; j++) {
            int ri = rp + 16 * j;
            __nv_bfloat162 p = __floats2bfloat162_rn(sh[ri][ci], sh[ri + 1][ci]);
            *(unsigned*)&O[(size_t)(Tc + ci) * ND + Tr + ri] = *(unsigned*)&p;
        }
    }
}

// ---------------- index extraction: one warp per (b,t) ----------------
__global__ void extract_idx_kernel(const void* __restrict__ mraw) {
    int bt = blockIdx.x;
    int b = bt / NT, t = bt % NT;
    int lane = threadIdx.x;
    int flags = g_flags;
    int fmt = (flags & (4 | 8)) ? 3 : (flags & 2) ? 2 : (flags & 1) ? 1 : 0;
    int cnt = 0;
    const size_t base = (size_t)b * NV * NT + t;
    for (int c = 0; c < NV / 32; c++) {
        int v = c * 32 + lane;
        size_t e = base + (size_t)v * NT;
        bool on;
        if (fmt == 0)      on = ((const int*)mraw)[e] != 0;
        else if (fmt == 1) on = ((const unsigned char*)mraw)[e] != 0;
        else if (fmt == 2) on = ((const float*)mraw)[e] != 0.0f;
        else               on = ((const unsigned short*)mraw)[e] != 0;
        unsigned bal = __ballot_sync(0xFFFFFFFFu, on);
        if (on) {
            int pos = cnt + __popc(bal & ((1u << lane) - 1u));
            if (pos < NS) g_idx[bt * NS + pos] = v;
        }
        cnt += __popc(bal);
    }
    if (cnt > NS) cnt = NS;
    for (int s = cnt + lane; s < NS; s += 32) g_idx[bt * NS + s] = NV;
}

// ---------------- bf16 3-stage pipelined tensor GEMM (TRANSB layout) --------
// B is (N x K) row-major k-contiguous. BM=64, BK=32, 256 thr = 8 warps (2x4).
// MODE 0: fused P GEMMs, bf16 out.
//   z=0: C=P1   = A0(Wu16)@B0(WkT16)^T : M=256,N=1024; bid -> (by=bid>>5, bx=bid&31)
//   z=1: C=P2^T = A1(WvT16)@B1(Wu16)^T : M=1024,N=256; bid -> (by=bid>>3, bx=bid&7)
// MODE 1: z = K-half split; C += z*csz (fp32)
// MODE 2: EPI: C = acc + wrow[r]*bocol[c] + Xadd[r*ldc+c] (fp32)
template <int BN, int MODE>
__global__ __launch_bounds__(256) void bgemm_kernel(
        const __nv_bfloat16* __restrict__ A0,
        const __nv_bfloat16* __restrict__ A1,
        const __nv_bfloat16* __restrict__ B0,
        const __nv_bfloat16* __restrict__ B1,
        void* __restrict__ C0, void* __restrict__ C1,
        int kiter, int lda, int ldb, int ldc, int csz,
        const float* __restrict__ wrow,
        const float* __restrict__ bocol,
        const float* __restrict__ Xadd) {
    constexpr int BM = 64, BK = 32, STR = 40;   // word-stride 20 -> conflict-free
    constexpr int WN = BN / 4, NI = (WN + 7) / 8;
    __shared__ __nv_bfloat16 smA[3][BM * STR];
    __shared__ __nv_bfloat16 smB[3][BN * STR];

    const __nv_bfloat16* Ap = A0;
    const __nv_bfloat16* Bp = B0;
    void* Cp = C0;
    int row0, col0;
    if (MODE == 0) {
        int bid = blockIdx.x;
        if (blockIdx.z == 0) {
            row0 = (bid >> 5) * BM; col0 = (bid & 31) * BN;
        } else {
            Ap = A1; Bp = B1; Cp = C1;
            ldc = NCV;
            row0 = (bid >> 3) * BM; col0 = (bid & 7) * BN;
        }
    } else {
        row0 = blockIdx.y * BM; col0 = blockIdx.x * BN;
        if (MODE == 1) {
            int kb = blockIdx.z * (kiter * BK);
            Ap = A0 + kb; Bp = B0 + kb;
            Cp = (float*)C0 + (size_t)blockIdx.z * csz;
        }
    }

    int tid = threadIdx.x;
    int warp = tid >> 5, lane = tid & 31;
    int wm = warp >> 2, wn = warp & 3;
    int g = lane >> 2, tg = lane & 3;

    float acc[2][NI][4] = {};

    auto load_stage = [&](int s, int k0) {
        {
            int m = tid >> 2, kq = tid & 3;      // 64 rows x 4 x cp16
            cp16(&smA[s][m * STR + kq * 8],
                 &Ap[(size_t)(row0 + m) * lda + k0 + kq * 8]);
        }
        if (BN == 64 || tid < 128) {
            int n = tid >> 2, kq = tid & 3;
            cp16(&smB[s][n * STR + kq * 8],
                 &Bp[(size_t)(col0 + n) * ldb + k0 + kq * 8]);
        }
        cp_commit();
    };

    load_stage(0, 0);
    load_stage(1, BK);

    for (int it = 0; it < kiter; it++) {
        cp_wait1();
        __syncthreads();
        if (it + 2 < kiter) load_stage((it + 2) % 3, (it + 2) * BK);
        else                cp_commit();

        const __nv_bfloat16* As_ = smA[it % 3];
        const __nv_bfloat16* Bs_ = smB[it % 3];
        #pragma unroll
        for (int ks = 0; ks < BK; ks += 16) {
            unsigned a[2][4];
            #pragma unroll
            for (int mi = 0; mi < 2; mi++) {
                int r = wm * 32 + mi * 16;
                a[mi][0] = *(const unsigned*)&As_[(r + g) * STR + ks + 2 * tg];
                a[mi][1] = *(const unsigned*)&As_[(r + 8 + g) * STR + ks + 2 * tg];
                a[mi][2] = *(const unsigned*)&As_[(r + g) * STR + ks + 8 + 2 * tg];
                a[mi][3] = *(const unsigned*)&As_[(r + 8 + g) * STR + ks + 8 + 2 * tg];
            }
            unsigned b[NI][2];
            #pragma unroll
            for (int ni = 0; ni < NI; ni++) {
                int c = wn * WN + ni * 8 + g;
                b[ni][0] = *(const unsigned*)&Bs_[c * STR + ks + 2 * tg];
                b[ni][1] = *(const unsigned*)&Bs_[c * STR + ks + 8 + 2 * tg];
            }
            #pragma unroll
            for (int mi = 0; mi < 2; mi++)
                #pragma unroll
                for (int ni = 0; ni < NI; ni++)
                    mma_bf16(acc[mi][ni], a[mi], b[ni]);
        }
        __syncthreads();
    }

    #pragma unroll
    for (int mi = 0; mi < 2; mi++) {
        #pragma unroll
        for (int ni = 0; ni < NI; ni++) {
            int r = row0 + wm * 32 + mi * 16 + g;
            int c = col0 + wn * WN + ni * 8 + tg * 2;
            float* a4 = acc[mi][ni];
            #pragma unroll
            for (int h = 0; h < 2; h++) {
                int rr = r + h * 8;
                float v0 = a4[h * 2], v1 = a4[h * 2 + 1];
                if (MODE == 0) {
                    __nv_bfloat162 p = __floats2bfloat162_rn(v0, v1);
                    *(unsigned*)&((__nv_bfloat16*)Cp)[(size_t)rr * ldc + c] =
                        *(unsigned*)&p;
                } else {
                    if (MODE == 2) {
                        float wr = wrow[rr];
                        v0 += wr * bocol[c]     + Xadd[(size_t)rr * ldc + c];
                        v1 += wr * bocol[c + 1] + Xadd[(size_t)rr * ldc + c + 1];
                    }
                    ((float*)Cp)[(size_t)rr * ldc + c]     = v0;
                    ((float*)Cp)[(size_t)rr * ldc + c + 1] = v1;
                }
            }
        }
    }
}

// ---------------- qk: gather-dot (bf16 vision) + softmax stats ----------------
__global__ void qk_kernel(const float* __restrict__ x) {
    int bt = blockIdx.x, b = bt / NT;
    __shared__ float zs[NCV];
    __shared__ float red[256];
    __shared__ float qks[NS];
    int tid = threadIdx.x;
    zs[tid] = g_Zh[0][bt * NCV + tid] + g_Zh[1][bt * NCV + tid];
    const float* xr = x + (size_t)bt * ND;
    float p = 0.f;
    #pragma unroll
    for (int i = tid; i < ND; i += 256) p += g_rvec[i] * xr[i];
    red[tid] = p;
    __syncthreads();
    for (int o = 128; o > 0; o >>= 1) {
        if (tid < o) red[tid] += red[tid + o];
        __syncthreads();
    }
    float c0 = red[0];

    int w = tid >> 5, lane = tid & 31;
    const __nv_bfloat16* vb = g_vis16 + (size_t)b * NV * NCV;
    #pragma unroll
    for (int q = 0; q < 8; q++) {
        int s = w * 8 + q;
        int vidx = g_idx[bt * NS + s];
        float d = 0.f;
        if (vidx < NV) {
            const __nv_bfloat16* vr = vb + (size_t)vidx * NCV;
            #pragma unroll
            for (int i = 0; i < 4; i++) {
                int e = 2 * lane + 64 * i;
                __nv_bfloat162 pv = *(const __nv_bfloat162*)&vr[e];
                d += __bfloat162float(pv.x) * zs[e]
                   + __bfloat162float(pv.y) * zs[e + 1];
            }
        }
        for (int o = 16; o > 0; o >>= 1) d += __shfl_down_sync(0xFFFFFFFFu, d, o);
        if (lane == 0) {
            float qk = (vidx < NV) ? (d + c0) * (1.f / 32.f) - 100.f
                                   : c0 * (1.f / 32.f);
            qks[s] = qk;
            g_qk[bt * NS + s] = qk;
        }
    }
    __syncthreads();
    if (w == 0) {
        float q1 = qks[lane], q2 = qks[lane + 32];
        float mx = fmaxf(q1, q2);
        for (int o = 16; o > 0; o >>= 1)
            mx = fmaxf(mx, __shfl_xor_sync(0xFFFFFFFFu, mx, o));
        float l = expf(q1 - mx) + expf(q2 - mx);
        for (int o = 16; o > 0; o >>= 1) l += __shfl_xor_sync(0xFFFFFFFFu, l, o);
        if (lane == 0) { g_m[bt] = mx; g_l[bt] = l; }
    }
}

// ------- G16 = sum_s p_s * vision16[idx_s] (batch softmax merge fused) -------
__global__ void gather_g_kernel() {
    int bt = blockIdx.x, b = bt / NT;
    __shared__ float ps[NS];
    __shared__ float red[256];
    int tid = threadIdx.x;

    float m = g_m[b * NT + tid];
    red[tid] = m;
    __syncthreads();
    for (int o = 128; o > 0; o >>= 1) {
        if (tid < o) red[tid] = fmaxf(red[tid], red[tid + o]);
        __syncthreads();
    }
    float M = red[0];
    __syncthreads();
    red[tid] = g_l[b * NT + tid] * expf(m - M);
    __syncthreads();
    for (int o = 128; o > 0; o >>= 1) {
        if (tid < o) red[tid] += red[tid + o];
        __syncthreads();
    }
    float invL = 1.f / red[0];

    if (tid < NS) ps[tid] = expf(g_qk[bt * NS + tid] - M) * invL;
    __syncthreads();
    if (tid == 0) {
        float s = 0.f;
        #pragma unroll
        for (int i = 0; i < NS; i++) s += ps[i];
        g_w[bt] = s;
    }
    float acc = 0.f;
    const __nv_bfloat16* vb = g_vis16 + (size_t)b * NV * NCV;
    const int* ids = &g_idx[bt * NS];
    #pragma unroll 4
    for (int s = 0; s < NS; s++) {
        int vi = ids[s];
        if (vi < NV) acc += ps[s] * __bfloat162float(vb[(size_t)vi * NCV + tid]);
    }
    g_G16[bt * NCV + tid] = __float2bfloat16(acc);
}

// ---------------- launch ----------------
extern "C" void kernel_launch(void* const* d_in, const int* in_sizes, int n_in,
                              void* d_out, int out_size) {
    const float* x      = (const float*)d_in[0];
    const float* vision = (const float*)d_in[1];
    const void*  mask   = d_in[2];
    const float* Wu     = (const float*)d_in[3];
    const float* bu     = (const float*)d_in[4];
    const float* Wk     = (const float*)d_in[5];
    const float* Wv     = (const float*)d_in[6];
    float* out = (float*)d_out;

    float *Zh;
    cudaGetSymbolAddress((void**)&Zh, g_Zh);
    __nv_bfloat16 *Wu16, *WkT16, *WvT16, *x16, *P1_16, *P2T16, *G16;
    cudaGetSymbolAddress((void**)&Wu16, g_Wu16);
    cudaGetSymbolAddress((void**)&WkT16, g_WkT16);
    cudaGetSymbolAddress((void**)&WvT16, g_WvT16);
    cudaGetSymbolAddress((void**)&x16, g_x16);
    cudaGetSymbolAddress((void**)&P1_16, g_P1_16);
    cudaGetSymbolAddress((void**)&P2T16, g_P2T16);
    cudaGetSymbolAddress((void**)&G16, g_G16);
    float *bo, *w;
    cudaGetSymbolAddress((void**)&bo, g_bo);
    cudaGetSymbolAddress((void**)&w, g_w);

    // 1) fused prep: detect + rbo + conversions + W transposes
    prep_kernel<<<4416, 256>>>(Wu, Wk, Wv, x, vision, bu, (const unsigned*)mask);
    // 2) selected-index lists
    extract_idx_kernel<<<NBT, 32>>>(mask);
    // 3) fused P GEMMs, direct bf16 output:
    //    z=0: P1 = Wu@Wk (M=256,N=1024); z=1: P2^T = WvT@Wu^T (M=1024,N=256)
    bgemm_kernel<32, 0><<<dim3(128, 1, 2), 256>>>(
        Wu16, WvT16, WkT16, Wu16, P1_16, P2T16,
        ND / 32, ND, ND, ND, 0, nullptr, nullptr, nullptr);
    // 4) Z halves: Z = X @ P1^T, split-K=2, BN=32
    bgemm_kernel<32, 1><<<dim3(NCV / 32, NBT / 64, 2), 256>>>(
        x16, nullptr, P1_16, nullptr, Zh, nullptr,
        512 / 32, ND, ND, NCV, NBT * NCV, nullptr, nullptr, nullptr);
    // 5) qk + per-token softmax stats
    qk_kernel<<<NBT, 256>>>(x);
    // 6) weighted gather G (batch softmax merge fused)
    gather_g_kernel<<<NBT, 256>>>();
    // 7) out = G @ P2 + w*bo + x   (B = P2^T, TRANSB, K=256)
    bgemm_kernel<64, 2><<<dim3(ND / 64, NBT / 64, 1), 256>>>(
        G16, nullptr, P2T16, nullptr, out, nullptr,
        NCV / 32, NCV, NCV, ND, 0, w, bo, x);
}